// round 14
// baseline (speedup 1.0000x reference)
#include <cuda_runtime.h>
#include <cuda_fp16.h>
#include <cstdint>
#include <math.h>

// Problem constants
#define GM 8192      // B*S
#define GN 1024      // D_MODEL
#define GK 1024      // D_MODEL
#define SQ 2048      // S
#define NB 4         // B
#define NH 16        // heads
#define DKH 64       // d_k per head

// Scratch (allocation-free rule: __device__ globals)
__device__ __half g_hQ[(size_t)GM * GN];
__device__ __half g_hK[(size_t)GM * GN];
__device__ __half g_hV[(size_t)GM * GN];
__device__ __half g_hC[(size_t)GM * GN];      // fp16 ctx
__device__ __half g_a16[3][(size_t)GM * GK];  // fp16 activations (q,k,v)
__device__ __half g_w16[3][(size_t)GN * GK];  // fp16 weights (Wq,Wk,Wv)
__device__ __half g_wo16[(size_t)GN * GK];    // fp16 Wo

__device__ __forceinline__ uint32_t smem_u32(const void* p) {
    uint32_t a;
    asm("{ .reg .u64 t; cvta.to.shared.u64 t, %1; cvt.u32.u64 %0, t; }"
        : "=r"(a) : "l"(p));
    return a;
}

__device__ __forceinline__ void cp_async16(uint32_t sm, const void* g) {
    asm volatile("cp.async.cg.shared.global [%0], [%1], 16;\n"
                 :: "r"(sm), "l"(g));
}
#define CP_COMMIT() asm volatile("cp.async.commit_group;\n" ::: "memory")
#define CP_WAIT(N)  asm volatile("cp.async.wait_group %0;\n" :: "n"(N) : "memory")

__device__ __forceinline__ void ldmx4(uint32_t* r, uint32_t addr) {
    asm volatile("ldmatrix.sync.aligned.m8n8.x4.shared.b16 {%0,%1,%2,%3}, [%4];"
                 : "=r"(r[0]), "=r"(r[1]), "=r"(r[2]), "=r"(r[3]) : "r"(addr));
}
__device__ __forceinline__ void ldmx4t(uint32_t* r, uint32_t addr) {
    asm volatile("ldmatrix.sync.aligned.m8n8.x4.trans.shared.b16 {%0,%1,%2,%3}, [%4];"
                 : "=r"(r[0]), "=r"(r[1]), "=r"(r[2]), "=r"(r[3]) : "r"(addr));
}

__device__ __forceinline__ void mma_fp(float* c, const uint32_t* a,
                                       uint32_t b0, uint32_t b1) {
    asm volatile(
        "mma.sync.aligned.m16n8k16.row.col.f32.f16.f16.f32 "
        "{%0,%1,%2,%3}, {%4,%5,%6,%7}, {%8,%9}, {%0,%1,%2,%3};"
        : "+f"(c[0]), "+f"(c[1]), "+f"(c[2]), "+f"(c[3])
        : "r"(a[0]), "r"(a[1]), "r"(a[2]), "r"(a[3]), "r"(b0), "r"(b1));
}

__device__ __forceinline__ uint32_t pack_h2(float x, float y) {
    const half2 h = __floats2half2_rn(x, y);
    return *reinterpret_cast<const uint32_t*>(&h);
}

// ============================================================================
// fp32 -> fp16 convert: all 7 tensors in ONE launch (z selects).
//   z 0..2: activations (n4_act elems), z 3..6: weights (n4_w elems).
// ============================================================================
__global__ __launch_bounds__(256) void conv_fp16_all(
    const float4* __restrict__ s0, const float4* __restrict__ s1,
    const float4* __restrict__ s2, const float4* __restrict__ s3,
    const float4* __restrict__ s4, const float4* __restrict__ s5,
    const float4* __restrict__ s6,
    half2* __restrict__ d0, half2* __restrict__ d1, half2* __restrict__ d2,
    half2* __restrict__ d3, half2* __restrict__ d4, half2* __restrict__ d5,
    half2* __restrict__ d6, int n4_act, int n4_w)
{
    const int z = blockIdx.y;
    const float4* src;
    half2* dst;
    int n4;
    switch (z) {
        case 0: src = s0; dst = d0; n4 = n4_act; break;
        case 1: src = s1; dst = d1; n4 = n4_act; break;
        case 2: src = s2; dst = d2; n4 = n4_act; break;
        case 3: src = s3; dst = d3; n4 = n4_w;   break;
        case 4: src = s4; dst = d4; n4 = n4_w;   break;
        case 5: src = s5; dst = d5; n4 = n4_w;   break;
        default: src = s6; dst = d6; n4 = n4_w;  break;
    }
    const int i = blockIdx.x * 256 + threadIdx.x;
    if (i >= n4) return;
    const float4 v = src[i];
    dst[2 * i]     = __floats2half2_rn(v.x, v.y);
    dst[2 * i + 1] = __floats2half2_rn(v.z, v.w);
}

// ============================================================================
// GEMM geometry (R9 measured-optimum): 128x128 CTA tile, 32x64 warp tile,
//   BK=32 per stage, 3 stages, 1 sync/iter, 2 CTAs/SM.
//   Prefetch issued right AFTER the barrier (overlaps full compute block).
// ============================================================================
#define BM 128
#define BN 128
#define BKC 32
#define PADK 40
#define GEMM_SMEM (3 * (BM + BN) * PADK * 2)   // 61440 B

// ============================================================================
// Single-pass fp16 GEMM for Q/K/V projections, fused via blockIdx.z.
// ============================================================================
__global__ __launch_bounds__(256, 2) void gemm_qkv_fp16(
    const __half* __restrict__ A0, const __half* __restrict__ A1,
    const __half* __restrict__ A2, const __half* __restrict__ W0,
    const __half* __restrict__ W1, const __half* __restrict__ W2,
    const float* __restrict__ b0p, const float* __restrict__ b1p,
    const float* __restrict__ b2p, __half* __restrict__ C0,
    __half* __restrict__ C1, __half* __restrict__ C2)
{
    extern __shared__ __half dynsm[];
    __half* smA = dynsm;                         // [3][BM*PADK]
    __half* smB = dynsm + 3 * BM * PADK;         // [3][BN*PADK]

    const int z = blockIdx.z;
    const __half* A = (z == 0) ? A0 : (z == 1) ? A1 : A2;
    const __half* W = (z == 0) ? W0 : (z == 1) ? W1 : W2;
    const float* bias = (z == 0) ? b0p : (z == 1) ? b1p : b2p;
    __half* C = (z == 0) ? C0 : (z == 1) ? C1 : C2;

    const int tid  = threadIdx.x;
    const int wid  = tid >> 5;
    const int lane = tid & 31;
    const int wm   = wid & 3;
    const int wn   = wid >> 2;
    const int m0   = blockIdx.y * BM;
    const int n0   = blockIdx.x * BN;

    const int crow = tid >> 1;
    const int cs0  = (tid & 1) * 2;
    const int lr = lane & 15;
    const int lc = (lane >> 4) * 8;

    float acc[2][8][4];
#pragma unroll
    for (int i = 0; i < 2; i++)
#pragma unroll
        for (int j = 0; j < 8; j++)
#pragma unroll
            for (int k = 0; k < 4; k++) acc[i][j][k] = 0.0f;

    const uint32_t smA0 = smem_u32(smA);
    const uint32_t smB0 = smem_u32(smB);

    auto issue_copy = [&](int it, int st) {
        const int kb = it * BKC;
        const __half* Ab = A + (size_t)(m0 + crow) * GK + kb;
        const __half* Bb = W + (size_t)(n0 + crow) * GK + kb;
        const uint32_t sa = smA0 + (st * BM * PADK + crow * PADK) * 2;
        const uint32_t sb = smB0 + (st * BN * PADK + crow * PADK) * 2;
#pragma unroll
        for (int s = 0; s < 2; s++) {
            cp_async16(sa + (cs0 + s) * 16, Ab + (cs0 + s) * 8);
            cp_async16(sb + (cs0 + s) * 16, Bb + (cs0 + s) * 8);
        }
        CP_COMMIT();
    };

    const int NIT1 = GK / BKC;   // 32
    issue_copy(0, 0);
    issue_copy(1, 1);

    for (int it = 0; it < NIT1; it++) {
        const int st = it % 3;
        if (it + 1 < NIT1) { CP_WAIT(1); } else { CP_WAIT(0); }
        __syncthreads();
        if (it + 2 < NIT1) issue_copy(it + 2, (it + 2) % 3);

        const uint32_t baseA = smA0 + st * BM * PADK * 2;
        const uint32_t baseB = smB0 + st * BN * PADK * 2;
#pragma unroll
        for (int ks = 0; ks < 2; ks++) {
            uint32_t a[2][4], b[4][4];
#pragma unroll
            for (int am = 0; am < 2; am++) {
                const int row = wm * 32 + am * 16 + lr;
                ldmx4(a[am], baseA + (row * PADK + ks * 16 + lc) * 2);
            }
#pragma unroll
            for (int bn = 0; bn < 4; bn++) {
                const int row = wn * 64 + bn * 16 + lr;
                ldmx4(b[bn], baseB + (row * PADK + ks * 16 + lc) * 2);
            }
#pragma unroll
            for (int am = 0; am < 2; am++)
#pragma unroll
                for (int bn = 0; bn < 4; bn++) {
                    mma_fp(acc[am][2 * bn + 0], a[am], b[bn][0], b[bn][2]);
                    mma_fp(acc[am][2 * bn + 1], a[am], b[bn][1], b[bn][3]);
                }
        }
    }

    const int er = lane >> 2;
    const int ec = (lane & 3) * 2;
#pragma unroll
    for (int am = 0; am < 2; am++) {
        const int row = m0 + wm * 32 + am * 16 + er;
#pragma unroll
        for (int bn = 0; bn < 8; bn++) {
            const int col = n0 + wn * 64 + bn * 8 + ec;
            const float bx = bias[col], by = bias[col + 1];
            *(half2*)(C + (size_t)row * GN + col) =
                __floats2half2_rn(acc[am][bn][0] + bx, acc[am][bn][1] + by);
            *(half2*)(C + (size_t)(row + 8) * GN + col) =
                __floats2half2_rn(acc[am][bn][2] + bx, acc[am][bn][3] + by);
        }
    }
}

// ============================================================================
// O projection: single-pass fp16 GEMM, fp32 out. Same geometry.
// ============================================================================
__global__ __launch_bounds__(256, 2) void gemm_o_fp16(
    const __half* __restrict__ A, const __half* __restrict__ W,
    const float* __restrict__ bias, float* __restrict__ C)
{
    extern __shared__ __half dynsm[];
    __half* smA = dynsm;
    __half* smB = dynsm + 3 * BM * PADK;

    const int tid  = threadIdx.x;
    const int wid  = tid >> 5;
    const int lane = tid & 31;
    const int wm   = wid & 3;
    const int wn   = wid >> 2;
    const int m0   = blockIdx.y * BM;
    const int n0   = blockIdx.x * BN;

    const int crow = tid >> 1;
    const int cs0  = (tid & 1) * 2;
    const int lr = lane & 15;
    const int lc = (lane >> 4) * 8;

    float acc[2][8][4];
#pragma unroll
    for (int i = 0; i < 2; i++)
#pragma unroll
        for (int j = 0; j < 8; j++)
#pragma unroll
            for (int k = 0; k < 4; k++) acc[i][j][k] = 0.0f;

    const uint32_t smA0 = smem_u32(smA);
    const uint32_t smB0 = smem_u32(smB);

    auto issue_copy = [&](int it, int st) {
        const int kb = it * BKC;
        const __half* Ab = A + (size_t)(m0 + crow) * GK + kb;
        const __half* Bb = W + (size_t)(n0 + crow) * GK + kb;
        const uint32_t sa = smA0 + (st * BM * PADK + crow * PADK) * 2;
        const uint32_t sb = smB0 + (st * BN * PADK + crow * PADK) * 2;
#pragma unroll
        for (int s = 0; s < 2; s++) {
            cp_async16(sa + (cs0 + s) * 16, Ab + (cs0 + s) * 8);
            cp_async16(sb + (cs0 + s) * 16, Bb + (cs0 + s) * 8);
        }
        CP_COMMIT();
    };

    const int NIT1 = GK / BKC;   // 32
    issue_copy(0, 0);
    issue_copy(1, 1);

    for (int it = 0; it < NIT1; it++) {
        const int st = it % 3;
        if (it + 1 < NIT1) { CP_WAIT(1); } else { CP_WAIT(0); }
        __syncthreads();
        if (it + 2 < NIT1) issue_copy(it + 2, (it + 2) % 3);

        const uint32_t baseA = smA0 + st * BM * PADK * 2;
        const uint32_t baseB = smB0 + st * BN * PADK * 2;
#pragma unroll
        for (int ks = 0; ks < 2; ks++) {
            uint32_t a[2][4], b[4][4];
#pragma unroll
            for (int am = 0; am < 2; am++) {
                const int row = wm * 32 + am * 16 + lr;
                ldmx4(a[am], baseA + (row * PADK + ks * 16 + lc) * 2);
            }
#pragma unroll
            for (int bn = 0; bn < 4; bn++) {
                const int row = wn * 64 + bn * 16 + lr;
                ldmx4(b[bn], baseB + (row * PADK + ks * 16 + lc) * 2);
            }
#pragma unroll
            for (int am = 0; am < 2; am++)
#pragma unroll
                for (int bn = 0; bn < 4; bn++) {
                    mma_fp(acc[am][2 * bn + 0], a[am], b[bn][0], b[bn][2]);
                    mma_fp(acc[am][2 * bn + 1], a[am], b[bn][1], b[bn][3]);
                }
        }
    }

    const int er = lane >> 2;
    const int ec = (lane & 3) * 2;
#pragma unroll
    for (int am = 0; am < 2; am++) {
        const int row = m0 + wm * 32 + am * 16 + er;
#pragma unroll
        for (int bn = 0; bn < 8; bn++) {
            const int col = n0 + wn * 64 + bn * 8 + ec;
            const float bx = bias[col], by = bias[col + 1];
            *(float2*)(C + (size_t)row * GN + col) =
                make_float2(acc[am][bn][0] + bx, acc[am][bn][1] + by);
            *(float2*)(C + (size_t)(row + 8) * GN + col) =
                make_float2(acc[am][bn][2] + bx, acc[am][bn][3] + by);
        }
    }
}

// ============================================================================
// Fused flash attention, fp16 mma.sync, BKV=128, register-resident P,
//   exp2-domain softmax, 3-stage K/V pipeline, ONE barrier per tile.
// ============================================================================
#define BQ 128
#define BKV 128
#define QS 72
#define NTKV (SQ / BKV)   // 16
#define NSTG 3
#define ATTN_SMEM ((BQ * QS + 2 * NSTG * BKV * QS) * 2)   // 129024 B
#define SC2 0.1803368801111f   // 0.125 * log2(e)

__global__ __launch_bounds__(256, 1) void attn_mma(
    const __half* __restrict__ Qh, const __half* __restrict__ Kh,
    const __half* __restrict__ Vh, __half* __restrict__ Ctx)
{
    extern __shared__ __half sm[];
    __half* sQ = sm;                      // [128][QS]
    __half* sK = sQ + BQ * QS;            // [3][128][QS]
    __half* sV = sK + NSTG * BKV * QS;    // [3][128][QS]

    const int tid  = threadIdx.x;
    const int wid  = tid >> 5;
    const int lane = tid & 31;
    const int lr   = lane & 15;
    const int lc   = (lane >> 4) * 8;
    const int er   = lane >> 2;
    const int ec   = (lane & 3) * 2;
    const int wrow = wid * 16;

    const int q0 = blockIdx.x * BQ;
    const size_t hb = ((size_t)blockIdx.z * SQ) * (size_t)GN + (size_t)blockIdx.y * DKH;

    const uint32_t sQb = smem_u32(sQ);
    const uint32_t sKb = smem_u32(sK);
    const uint32_t sVb = smem_u32(sV);

    const int crow = tid >> 1;
    const int cs0  = (tid & 1) * 4;

    auto loadKV = [&](int kt, int st) {
        const __half* kp = Kh + hb + (size_t)(kt * BKV + crow) * GN;
        const __half* vp = Vh + hb + (size_t)(kt * BKV + crow) * GN;
        const uint32_t dk = sKb + (st * BKV * QS + crow * QS) * 2;
        const uint32_t dv = sVb + (st * BKV * QS + crow * QS) * 2;
#pragma unroll
        for (int s = 0; s < 4; s++) {
            cp_async16(dk + (cs0 + s) * 16, kp + (cs0 + s) * 8);
            cp_async16(dv + (cs0 + s) * 16, vp + (cs0 + s) * 8);
        }
        CP_COMMIT();
    };

    {   // Q load (own commit group)
        const __half* qp = Qh + hb + (size_t)(q0 + crow) * GN;
        const uint32_t dq = sQb + (crow * QS) * 2;
#pragma unroll
        for (int s = 0; s < 4; s++)
            cp_async16(dq + (cs0 + s) * 16, qp + (cs0 + s) * 8);
        CP_COMMIT();
    }
    loadKV(0, 0);
    loadKV(1, 1);

    float m0r = -1.0e30f, m1r = -1.0e30f, l0 = 0.0f, l1 = 0.0f;
    float o[8][4];
#pragma unroll
    for (int j = 0; j < 8; j++)
#pragma unroll
        for (int k = 0; k < 4; k++) o[j][k] = 0.0f;

    uint32_t aq[4][4];   // Q fragments, loaded once

    for (int kt = 0; kt < NTKV; kt++) {
        if (kt < NTKV - 1) { CP_WAIT(1); } else { CP_WAIT(0); }
        __syncthreads();
        // 3-stage: write target (kt+2)%3 != read stage kt%3; all warps are
        // past tile kt-1 (barrier above), so its reads of (kt+2)%3 are done.
        if (kt + 2 < NTKV) loadKV(kt + 2, (kt + 2) % NSTG);
        if (kt == 0) {
#pragma unroll
            for (int ks = 0; ks < 4; ks++)
                ldmx4(aq[ks], sQb + ((wrow + lr) * QS + ks * 16 + lc) * 2);
        }
        const int st = kt % NSTG;
        const uint32_t kbase = sKb + st * BKV * QS * 2;
        const uint32_t vbase = sVb + st * BKV * QS * 2;

        // ---- S = Q K^T (16 x 128 per warp) ----
        float s[16][4];
#pragma unroll
        for (int t = 0; t < 16; t++)
#pragma unroll
            for (int k = 0; k < 4; k++) s[t][k] = 0.0f;

#pragma unroll
        for (int ks = 0; ks < 4; ks++) {
#pragma unroll
            for (int nt = 0; nt < 8; nt++) {
                uint32_t b[4];
                ldmx4(b, kbase + ((nt * 16 + lr) * QS + ks * 16 + lc) * 2);
                mma_fp(s[2 * nt + 0], aq[ks], b[0], b[2]);
                mma_fp(s[2 * nt + 1], aq[ks], b[1], b[3]);
            }
        }

        // ---- online softmax in log2 domain; P packed into A-frags ----
        float mx0 = -1.0e30f, mx1 = -1.0e30f;
#pragma unroll
        for (int t = 0; t < 16; t++) {
            mx0 = fmaxf(mx0, fmaxf(s[t][0], s[t][1]));
            mx1 = fmaxf(mx1, fmaxf(s[t][2], s[t][3]));
        }
        mx0 = fmaxf(mx0, __shfl_xor_sync(0xffffffffu, mx0, 1));
        mx0 = fmaxf(mx0, __shfl_xor_sync(0xffffffffu, mx0, 2));
        mx1 = fmaxf(mx1, __shfl_xor_sync(0xffffffffu, mx1, 1));
        mx1 = fmaxf(mx1, __shfl_xor_sync(0xffffffffu, mx1, 2));
        mx0 *= SC2;
        mx1 *= SC2;
        const float mn0 = fmaxf(m0r, mx0);
        const float mn1 = fmaxf(m1r, mx1);
        const float c0 = exp2f(m0r - mn0);
        const float c1 = exp2f(m1r - mn1);

        float rs0 = 0.0f, rs1 = 0.0f;
        uint32_t pw[16][2];
#pragma unroll
        for (int t = 0; t < 16; t++) {
            const float p00 = exp2f(fmaf(s[t][0], SC2, -mn0));
            const float p01 = exp2f(fmaf(s[t][1], SC2, -mn0));
            const float p10 = exp2f(fmaf(s[t][2], SC2, -mn1));
            const float p11 = exp2f(fmaf(s[t][3], SC2, -mn1));
            rs0 += p00 + p01;
            rs1 += p10 + p11;
            pw[t][0] = pack_h2(p00, p01);
            pw[t][1] = pack_h2(p10, p11);
        }
        rs0 += __shfl_xor_sync(0xffffffffu, rs0, 1);
        rs0 += __shfl_xor_sync(0xffffffffu, rs0, 2);
        rs1 += __shfl_xor_sync(0xffffffffu, rs1, 1);
        rs1 += __shfl_xor_sync(0xffffffffu, rs1, 2);
        l0 = l0 * c0 + rs0;
        l1 = l1 * c1 + rs1;
        m0r = mn0;
        m1r = mn1;
#pragma unroll
        for (int j = 0; j < 8; j++) {
            o[j][0] *= c0; o[j][1] *= c0;
            o[j][2] *= c1; o[j][3] *= c1;
        }

        // ---- O += P V (P from registers, V via ldmatrix.trans) ----
#pragma unroll
        for (int j = 0; j < 8; j++) {      // 16-key chunks
            const uint32_t pa[4] = {pw[2 * j][0], pw[2 * j][1],
                                    pw[2 * j + 1][0], pw[2 * j + 1][1]};
#pragma unroll
            for (int dt = 0; dt < 4; dt++) {
                uint32_t vb[4];
                ldmx4t(vb, vbase + ((j * 16 + lr) * QS + dt * 16 + lc) * 2);
                mma_fp(o[2 * dt + 0], pa, vb[0], vb[1]);
                mma_fp(o[2 * dt + 1], pa, vb[2], vb[3]);
            }
        }
    }

    const float inv0 = 1.0f / l0;
    const float inv1 = 1.0f / l1;
    const int row0 = q0 + wrow + er;
#pragma unroll
    for (int j = 0; j < 8; j++) {
        const int col = j * 8 + ec;
        __half* p0 = Ctx + hb + (size_t)row0 * GN + col;
        __half* p1 = Ctx + hb + (size_t)(row0 + 8) * GN + col;
        *(half2*)p0 = __floats2half2_rn(o[j][0] * inv0, o[j][1] * inv0);
        *(half2*)p1 = __floats2half2_rn(o[j][2] * inv1, o[j][3] * inv1);
    }
}

// ============================================================================
// Launch
// ============================================================================
extern "C" void kernel_launch(void* const* d_in, const int* in_sizes, int n_in,
                              void* d_out, int out_size)
{
    const float* q  = (const float*)d_in[0];
    const float* k  = (const float*)d_in[1];
    const float* v  = (const float*)d_in[2];
    const float* Wq = (const float*)d_in[3];
    const float* bq = (const float*)d_in[4];
    const float* Wk = (const float*)d_in[5];
    const float* bk = (const float*)d_in[6];
    const float* Wv = (const float*)d_in[7];
    const float* bv = (const float*)d_in[8];
    const float* Wo = (const float*)d_in[9];
    const float* bo = (const float*)d_in[10];
    float* out = (float*)d_out;

    __half *hQ, *hK, *hV, *hC, *a16, *w16, *wo16;
    cudaGetSymbolAddress((void**)&hQ, g_hQ);
    cudaGetSymbolAddress((void**)&hK, g_hK);
    cudaGetSymbolAddress((void**)&hV, g_hV);
    cudaGetSymbolAddress((void**)&hC, g_hC);
    cudaGetSymbolAddress((void**)&a16, g_a16);
    cudaGetSymbolAddress((void**)&w16, g_w16);
    cudaGetSymbolAddress((void**)&wo16, g_wo16);

    __half* a0 = a16;
    __half* a1 = a16 + (size_t)GM * GK;
    __half* a2 = a16 + 2 * (size_t)GM * GK;
    __half* w0 = w16;
    __half* w1 = w16 + (size_t)GN * GK;
    __half* w2 = w16 + 2 * (size_t)GN * GK;

    const int n4_act = GM * GK / 4;
    const int n4_w   = GN * GK / 4;

    // All 7 fp32->fp16 conversions in one launch
    conv_fp16_all<<<dim3(n4_act / 256, 7), 256>>>(
        (const float4*)q, (const float4*)k, (const float4*)v,
        (const float4*)Wq, (const float4*)Wk, (const float4*)Wv,
        (const float4*)Wo,
        (half2*)a0, (half2*)a1, (half2*)a2,
        (half2*)w0, (half2*)w1, (half2*)w2, (half2*)wo16,
        n4_act, n4_w);

    cudaFuncSetAttribute(gemm_qkv_fp16, cudaFuncAttributeMaxDynamicSharedMemorySize, GEMM_SMEM);
    cudaFuncSetAttribute(gemm_o_fp16, cudaFuncAttributeMaxDynamicSharedMemorySize, GEMM_SMEM);

    gemm_qkv_fp16<<<dim3(GN / BN, GM / BM, 3), 256, GEMM_SMEM>>>(
        a0, a1, a2, w0, w1, w2, bq, bk, bv, hQ, hK, hV);

    cudaFuncSetAttribute(attn_mma, cudaFuncAttributeMaxDynamicSharedMemorySize, ATTN_SMEM);
    attn_mma<<<dim3(SQ / BQ, NH, NB), 256, ATTN_SMEM>>>(hQ, hK, hV, hC);

    gemm_o_fp16<<<dim3(GN / BN, GM / BM), 256, GEMM_SMEM>>>(hC, wo16, bo, out);
}

// round 15
// speedup vs baseline: 1.0349x; 1.0349x over previous
#include <cuda_runtime.h>
#include <cuda_fp16.h>
#include <cstdint>
#include <math.h>

// Problem constants
#define GM 8192      // B*S
#define GN 1024      // D_MODEL
#define GK 1024      // D_MODEL
#define SQ 2048      // S
#define NB 4         // B
#define NH 16        // heads
#define DKH 64       // d_k per head

// Scratch (allocation-free rule: __device__ globals)
__device__ __half g_hQ[(size_t)GM * GN];
__device__ __half g_hK[(size_t)GM * GN];
__device__ __half g_hV[(size_t)GM * GN];
__device__ __half g_hC[(size_t)GM * GN];      // fp16 ctx
__device__ __half g_a16[3][(size_t)GM * GK];  // fp16 activations (q,k,v)
__device__ __half g_w16[3][(size_t)GN * GK];  // fp16 weights (Wq,Wk,Wv)
__device__ __half g_wo16[(size_t)GN * GK];    // fp16 Wo

__device__ __forceinline__ uint32_t smem_u32(const void* p) {
    uint32_t a;
    asm("{ .reg .u64 t; cvta.to.shared.u64 t, %1; cvt.u32.u64 %0, t; }"
        : "=r"(a) : "l"(p));
    return a;
}

__device__ __forceinline__ void cp_async16(uint32_t sm, const void* g) {
    asm volatile("cp.async.cg.shared.global [%0], [%1], 16;\n"
                 :: "r"(sm), "l"(g));
}
#define CP_COMMIT() asm volatile("cp.async.commit_group;\n" ::: "memory")
#define CP_WAIT(N)  asm volatile("cp.async.wait_group %0;\n" :: "n"(N) : "memory")

__device__ __forceinline__ void ldmx4(uint32_t* r, uint32_t addr) {
    asm volatile("ldmatrix.sync.aligned.m8n8.x4.shared.b16 {%0,%1,%2,%3}, [%4];"
                 : "=r"(r[0]), "=r"(r[1]), "=r"(r[2]), "=r"(r[3]) : "r"(addr));
}
__device__ __forceinline__ void ldmx4t(uint32_t* r, uint32_t addr) {
    asm volatile("ldmatrix.sync.aligned.m8n8.x4.trans.shared.b16 {%0,%1,%2,%3}, [%4];"
                 : "=r"(r[0]), "=r"(r[1]), "=r"(r[2]), "=r"(r[3]) : "r"(addr));
}

__device__ __forceinline__ void mma_fp(float* c, const uint32_t* a,
                                       uint32_t b0, uint32_t b1) {
    asm volatile(
        "mma.sync.aligned.m16n8k16.row.col.f32.f16.f16.f32 "
        "{%0,%1,%2,%3}, {%4,%5,%6,%7}, {%8,%9}, {%0,%1,%2,%3};"
        : "+f"(c[0]), "+f"(c[1]), "+f"(c[2]), "+f"(c[3])
        : "r"(a[0]), "r"(a[1]), "r"(a[2]), "r"(a[3]), "r"(b0), "r"(b1));
}

__device__ __forceinline__ uint32_t pack_h2(float x, float y) {
    const half2 h = __floats2half2_rn(x, y);
    return *reinterpret_cast<const uint32_t*>(&h);
}

// ============================================================================
// fp32 -> fp16 converts (R12 form: separate launches)
// ============================================================================
__global__ __launch_bounds__(256) void conv_fp16_x3(
    const float4* __restrict__ s0, const float4* __restrict__ s1,
    const float4* __restrict__ s2, half2* __restrict__ d0,
    half2* __restrict__ d1, half2* __restrict__ d2, int n4)
{
    const int z = blockIdx.y;
    const float4* src = (z == 0) ? s0 : (z == 1) ? s1 : s2;
    half2* dst = (z == 0) ? d0 : (z == 1) ? d1 : d2;
    const int i = blockIdx.x * 256 + threadIdx.x;
    if (i >= n4) return;
    const float4 v = src[i];
    dst[2 * i]     = __floats2half2_rn(v.x, v.y);
    dst[2 * i + 1] = __floats2half2_rn(v.z, v.w);
}

__global__ __launch_bounds__(256) void conv_fp16_1(
    const float4* __restrict__ src, half2* __restrict__ dst, int n4)
{
    const int i = blockIdx.x * 256 + threadIdx.x;
    if (i >= n4) return;
    const float4 v = src[i];
    dst[2 * i]     = __floats2half2_rn(v.x, v.y);
    dst[2 * i + 1] = __floats2half2_rn(v.z, v.w);
}

// ============================================================================
// GEMM geometry (R9/R12 measured-optimum): 128x128 CTA tile, 32x64 warp tile,
//   BK=32 per stage, 3 stages, 1 sync/iter, 2 CTAs/SM.
//   Prefetch issued at END of iteration body (R12 measured-best placement).
// ============================================================================
#define BM 128
#define BN 128
#define BKC 32
#define PADK 40
#define GEMM_SMEM (3 * (BM + BN) * PADK * 2)   // 61440 B

// ============================================================================
// Single-pass fp16 GEMM for Q/K/V projections, fused via blockIdx.z.
// ============================================================================
__global__ __launch_bounds__(256, 2) void gemm_qkv_fp16(
    const __half* __restrict__ A0, const __half* __restrict__ A1,
    const __half* __restrict__ A2, const __half* __restrict__ W0,
    const __half* __restrict__ W1, const __half* __restrict__ W2,
    const float* __restrict__ b0p, const float* __restrict__ b1p,
    const float* __restrict__ b2p, __half* __restrict__ C0,
    __half* __restrict__ C1, __half* __restrict__ C2)
{
    extern __shared__ __half dynsm[];
    __half* smA = dynsm;                         // [3][BM*PADK]
    __half* smB = dynsm + 3 * BM * PADK;         // [3][BN*PADK]

    const int z = blockIdx.z;
    const __half* A = (z == 0) ? A0 : (z == 1) ? A1 : A2;
    const __half* W = (z == 0) ? W0 : (z == 1) ? W1 : W2;
    const float* bias = (z == 0) ? b0p : (z == 1) ? b1p : b2p;
    __half* C = (z == 0) ? C0 : (z == 1) ? C1 : C2;

    const int tid  = threadIdx.x;
    const int wid  = tid >> 5;
    const int lane = tid & 31;
    const int wm   = wid & 3;
    const int wn   = wid >> 2;
    const int m0   = blockIdx.y * BM;
    const int n0   = blockIdx.x * BN;

    const int crow = tid >> 1;
    const int cs0  = (tid & 1) * 2;
    const int lr = lane & 15;
    const int lc = (lane >> 4) * 8;

    float acc[2][8][4];
#pragma unroll
    for (int i = 0; i < 2; i++)
#pragma unroll
        for (int j = 0; j < 8; j++)
#pragma unroll
            for (int k = 0; k < 4; k++) acc[i][j][k] = 0.0f;

    const uint32_t smA0 = smem_u32(smA);
    const uint32_t smB0 = smem_u32(smB);

    auto issue_copy = [&](int it, int st) {
        const int kb = it * BKC;
        const __half* Ab = A + (size_t)(m0 + crow) * GK + kb;
        const __half* Bb = W + (size_t)(n0 + crow) * GK + kb;
        const uint32_t sa = smA0 + (st * BM * PADK + crow * PADK) * 2;
        const uint32_t sb = smB0 + (st * BN * PADK + crow * PADK) * 2;
#pragma unroll
        for (int s = 0; s < 2; s++) {
            cp_async16(sa + (cs0 + s) * 16, Ab + (cs0 + s) * 8);
            cp_async16(sb + (cs0 + s) * 16, Bb + (cs0 + s) * 8);
        }
        CP_COMMIT();
    };

    const int NIT1 = GK / BKC;   // 32
    issue_copy(0, 0);
    issue_copy(1, 1);

    for (int it = 0; it < NIT1; it++) {
        const int st = it % 3;
        if (it + 1 < NIT1) { CP_WAIT(1); } else { CP_WAIT(0); }
        __syncthreads();

        const uint32_t baseA = smA0 + st * BM * PADK * 2;
        const uint32_t baseB = smB0 + st * BN * PADK * 2;
#pragma unroll
        for (int ks = 0; ks < 2; ks++) {
            uint32_t a[2][4], b[4][4];
#pragma unroll
            for (int am = 0; am < 2; am++) {
                const int row = wm * 32 + am * 16 + lr;
                ldmx4(a[am], baseA + (row * PADK + ks * 16 + lc) * 2);
            }
#pragma unroll
            for (int bn = 0; bn < 4; bn++) {
                const int row = wn * 64 + bn * 16 + lr;
                ldmx4(b[bn], baseB + (row * PADK + ks * 16 + lc) * 2);
            }
#pragma unroll
            for (int am = 0; am < 2; am++)
#pragma unroll
                for (int bn = 0; bn < 4; bn++) {
                    mma_fp(acc[am][2 * bn + 0], a[am], b[bn][0], b[bn][2]);
                    mma_fp(acc[am][2 * bn + 1], a[am], b[bn][1], b[bn][3]);
                }
        }
        if (it + 2 < NIT1) issue_copy(it + 2, (it + 2) % 3);
    }

    const int er = lane >> 2;
    const int ec = (lane & 3) * 2;
#pragma unroll
    for (int am = 0; am < 2; am++) {
        const int row = m0 + wm * 32 + am * 16 + er;
#pragma unroll
        for (int bn = 0; bn < 8; bn++) {
            const int col = n0 + wn * 64 + bn * 8 + ec;
            const float bx = bias[col], by = bias[col + 1];
            *(half2*)(C + (size_t)row * GN + col) =
                __floats2half2_rn(acc[am][bn][0] + bx, acc[am][bn][1] + by);
            *(half2*)(C + (size_t)(row + 8) * GN + col) =
                __floats2half2_rn(acc[am][bn][2] + bx, acc[am][bn][3] + by);
        }
    }
}

// ============================================================================
// O projection: single-pass fp16 GEMM, fp32 out. Same (R12) geometry.
// ============================================================================
__global__ __launch_bounds__(256, 2) void gemm_o_fp16(
    const __half* __restrict__ A, const __half* __restrict__ W,
    const float* __restrict__ bias, float* __restrict__ C)
{
    extern __shared__ __half dynsm[];
    __half* smA = dynsm;
    __half* smB = dynsm + 3 * BM * PADK;

    const int tid  = threadIdx.x;
    const int wid  = tid >> 5;
    const int lane = tid & 31;
    const int wm   = wid & 3;
    const int wn   = wid >> 2;
    const int m0   = blockIdx.y * BM;
    const int n0   = blockIdx.x * BN;

    const int crow = tid >> 1;
    const int cs0  = (tid & 1) * 2;
    const int lr = lane & 15;
    const int lc = (lane >> 4) * 8;

    float acc[2][8][4];
#pragma unroll
    for (int i = 0; i < 2; i++)
#pragma unroll
        for (int j = 0; j < 8; j++)
#pragma unroll
            for (int k = 0; k < 4; k++) acc[i][j][k] = 0.0f;

    const uint32_t smA0 = smem_u32(smA);
    const uint32_t smB0 = smem_u32(smB);

    auto issue_copy = [&](int it, int st) {
        const int kb = it * BKC;
        const __half* Ab = A + (size_t)(m0 + crow) * GK + kb;
        const __half* Bb = W + (size_t)(n0 + crow) * GK + kb;
        const uint32_t sa = smA0 + (st * BM * PADK + crow * PADK) * 2;
        const uint32_t sb = smB0 + (st * BN * PADK + crow * PADK) * 2;
#pragma unroll
        for (int s = 0; s < 2; s++) {
            cp_async16(sa + (cs0 + s) * 16, Ab + (cs0 + s) * 8);
            cp_async16(sb + (cs0 + s) * 16, Bb + (cs0 + s) * 8);
        }
        CP_COMMIT();
    };

    const int NIT1 = GK / BKC;   // 32
    issue_copy(0, 0);
    issue_copy(1, 1);

    for (int it = 0; it < NIT1; it++) {
        const int st = it % 3;
        if (it + 1 < NIT1) { CP_WAIT(1); } else { CP_WAIT(0); }
        __syncthreads();

        const uint32_t baseA = smA0 + st * BM * PADK * 2;
        const uint32_t baseB = smB0 + st * BN * PADK * 2;
#pragma unroll
        for (int ks = 0; ks < 2; ks++) {
            uint32_t a[2][4], b[4][4];
#pragma unroll
            for (int am = 0; am < 2; am++) {
                const int row = wm * 32 + am * 16 + lr;
                ldmx4(a[am], baseA + (row * PADK + ks * 16 + lc) * 2);
            }
#pragma unroll
            for (int bn = 0; bn < 4; bn++) {
                const int row = wn * 64 + bn * 16 + lr;
                ldmx4(b[bn], baseB + (row * PADK + ks * 16 + lc) * 2);
            }
#pragma unroll
            for (int am = 0; am < 2; am++)
#pragma unroll
                for (int bn = 0; bn < 4; bn++) {
                    mma_fp(acc[am][2 * bn + 0], a[am], b[bn][0], b[bn][2]);
                    mma_fp(acc[am][2 * bn + 1], a[am], b[bn][1], b[bn][3]);
                }
        }
        if (it + 2 < NIT1) issue_copy(it + 2, (it + 2) % 3);
    }

    const int er = lane >> 2;
    const int ec = (lane & 3) * 2;
#pragma unroll
    for (int am = 0; am < 2; am++) {
        const int row = m0 + wm * 32 + am * 16 + er;
#pragma unroll
        for (int bn = 0; bn < 8; bn++) {
            const int col = n0 + wn * 64 + bn * 8 + ec;
            const float bx = bias[col], by = bias[col + 1];
            *(float2*)(C + (size_t)row * GN + col) =
                make_float2(acc[am][bn][0] + bx, acc[am][bn][1] + by);
            *(float2*)(C + (size_t)(row + 8) * GN + col) =
                make_float2(acc[am][bn][2] + bx, acc[am][bn][3] + by);
        }
    }
}

// ============================================================================
// Fused flash attention, fp16 mma.sync, BKV=128, register-resident P,
//   exp2-domain softmax, 3-stage K/V pipeline, ONE barrier per tile.
//   (The single change vs the 621us R12 baseline.)
// ============================================================================
#define BQ 128
#define BKV 128
#define QS 72
#define NTKV (SQ / BKV)   // 16
#define NSTG 3
#define ATTN_SMEM ((BQ * QS + 2 * NSTG * BKV * QS) * 2)   // 129024 B
#define SC2 0.1803368801111f   // 0.125 * log2(e)

__global__ __launch_bounds__(256, 1) void attn_mma(
    const __half* __restrict__ Qh, const __half* __restrict__ Kh,
    const __half* __restrict__ Vh, __half* __restrict__ Ctx)
{
    extern __shared__ __half sm[];
    __half* sQ = sm;                      // [128][QS]
    __half* sK = sQ + BQ * QS;            // [3][128][QS]
    __half* sV = sK + NSTG * BKV * QS;    // [3][128][QS]

    const int tid  = threadIdx.x;
    const int wid  = tid >> 5;
    const int lane = tid & 31;
    const int lr   = lane & 15;
    const int lc   = (lane >> 4) * 8;
    const int er   = lane >> 2;
    const int ec   = (lane & 3) * 2;
    const int wrow = wid * 16;

    const int q0 = blockIdx.x * BQ;
    const size_t hb = ((size_t)blockIdx.z * SQ) * (size_t)GN + (size_t)blockIdx.y * DKH;

    const uint32_t sQb = smem_u32(sQ);
    const uint32_t sKb = smem_u32(sK);
    const uint32_t sVb = smem_u32(sV);

    const int crow = tid >> 1;
    const int cs0  = (tid & 1) * 4;

    auto loadKV = [&](int kt, int st) {
        const __half* kp = Kh + hb + (size_t)(kt * BKV + crow) * GN;
        const __half* vp = Vh + hb + (size_t)(kt * BKV + crow) * GN;
        const uint32_t dk = sKb + (st * BKV * QS + crow * QS) * 2;
        const uint32_t dv = sVb + (st * BKV * QS + crow * QS) * 2;
#pragma unroll
        for (int s = 0; s < 4; s++) {
            cp_async16(dk + (cs0 + s) * 16, kp + (cs0 + s) * 8);
            cp_async16(dv + (cs0 + s) * 16, vp + (cs0 + s) * 8);
        }
        CP_COMMIT();
    };

    {   // Q load (own commit group)
        const __half* qp = Qh + hb + (size_t)(q0 + crow) * GN;
        const uint32_t dq = sQb + (crow * QS) * 2;
#pragma unroll
        for (int s = 0; s < 4; s++)
            cp_async16(dq + (cs0 + s) * 16, qp + (cs0 + s) * 8);
        CP_COMMIT();
    }
    loadKV(0, 0);
    loadKV(1, 1);

    float m0r = -1.0e30f, m1r = -1.0e30f, l0 = 0.0f, l1 = 0.0f;
    float o[8][4];
#pragma unroll
    for (int j = 0; j < 8; j++)
#pragma unroll
        for (int k = 0; k < 4; k++) o[j][k] = 0.0f;

    uint32_t aq[4][4];   // Q fragments, loaded once

    for (int kt = 0; kt < NTKV; kt++) {
        if (kt < NTKV - 1) { CP_WAIT(1); } else { CP_WAIT(0); }
        __syncthreads();
        // 3-stage: write target (kt+2)%3 equals the stage read in tile kt-1,
        // whose readers are all past the barrier above -> safe, no 2nd barrier.
        if (kt + 2 < NTKV) loadKV(kt + 2, (kt + 2) % NSTG);
        if (kt == 0) {
#pragma unroll
            for (int ks = 0; ks < 4; ks++)
                ldmx4(aq[ks], sQb + ((wrow + lr) * QS + ks * 16 + lc) * 2);
        }
        const int st = kt % NSTG;
        const uint32_t kbase = sKb + st * BKV * QS * 2;
        const uint32_t vbase = sVb + st * BKV * QS * 2;

        // ---- S = Q K^T (16 x 128 per warp) ----
        float s[16][4];
#pragma unroll
        for (int t = 0; t < 16; t++)
#pragma unroll
            for (int k = 0; k < 4; k++) s[t][k] = 0.0f;

#pragma unroll
        for (int ks = 0; ks < 4; ks++) {
#pragma unroll
            for (int nt = 0; nt < 8; nt++) {
                uint32_t b[4];
                ldmx4(b, kbase + ((nt * 16 + lr) * QS + ks * 16 + lc) * 2);
                mma_fp(s[2 * nt + 0], aq[ks], b[0], b[2]);
                mma_fp(s[2 * nt + 1], aq[ks], b[1], b[3]);
            }
        }

        // ---- online softmax in log2 domain; P packed into A-frags ----
        float mx0 = -1.0e30f, mx1 = -1.0e30f;
#pragma unroll
        for (int t = 0; t < 16; t++) {
            mx0 = fmaxf(mx0, fmaxf(s[t][0], s[t][1]));
            mx1 = fmaxf(mx1, fmaxf(s[t][2], s[t][3]));
        }
        mx0 = fmaxf(mx0, __shfl_xor_sync(0xffffffffu, mx0, 1));
        mx0 = fmaxf(mx0, __shfl_xor_sync(0xffffffffu, mx0, 2));
        mx1 = fmaxf(mx1, __shfl_xor_sync(0xffffffffu, mx1, 1));
        mx1 = fmaxf(mx1, __shfl_xor_sync(0xffffffffu, mx1, 2));
        mx0 *= SC2;
        mx1 *= SC2;
        const float mn0 = fmaxf(m0r, mx0);
        const float mn1 = fmaxf(m1r, mx1);
        const float c0 = exp2f(m0r - mn0);
        const float c1 = exp2f(m1r - mn1);

        float rs0 = 0.0f, rs1 = 0.0f;
        uint32_t pw[16][2];
#pragma unroll
        for (int t = 0; t < 16; t++) {
            const float p00 = exp2f(fmaf(s[t][0], SC2, -mn0));
            const float p01 = exp2f(fmaf(s[t][1], SC2, -mn0));
            const float p10 = exp2f(fmaf(s[t][2], SC2, -mn1));
            const float p11 = exp2f(fmaf(s[t][3], SC2, -mn1));
            rs0 += p00 + p01;
            rs1 += p10 + p11;
            pw[t][0] = pack_h2(p00, p01);
            pw[t][1] = pack_h2(p10, p11);
        }
        rs0 += __shfl_xor_sync(0xffffffffu, rs0, 1);
        rs0 += __shfl_xor_sync(0xffffffffu, rs0, 2);
        rs1 += __shfl_xor_sync(0xffffffffu, rs1, 1);
        rs1 += __shfl_xor_sync(0xffffffffu, rs1, 2);
        l0 = l0 * c0 + rs0;
        l1 = l1 * c1 + rs1;
        m0r = mn0;
        m1r = mn1;
#pragma unroll
        for (int j = 0; j < 8; j++) {
            o[j][0] *= c0; o[j][1] *= c0;
            o[j][2] *= c1; o[j][3] *= c1;
        }

        // ---- O += P V (P from registers, V via ldmatrix.trans) ----
#pragma unroll
        for (int j = 0; j < 8; j++) {      // 16-key chunks
            const uint32_t pa[4] = {pw[2 * j][0], pw[2 * j][1],
                                    pw[2 * j + 1][0], pw[2 * j + 1][1]};
#pragma unroll
            for (int dt = 0; dt < 4; dt++) {
                uint32_t vb[4];
                ldmx4t(vb, vbase + ((j * 16 + lr) * QS + dt * 16 + lc) * 2);
                mma_fp(o[2 * dt + 0], pa, vb[0], vb[1]);
                mma_fp(o[2 * dt + 1], pa, vb[2], vb[3]);
            }
        }
    }

    const float inv0 = 1.0f / l0;
    const float inv1 = 1.0f / l1;
    const int row0 = q0 + wrow + er;
#pragma unroll
    for (int j = 0; j < 8; j++) {
        const int col = j * 8 + ec;
        __half* p0 = Ctx + hb + (size_t)row0 * GN + col;
        __half* p1 = Ctx + hb + (size_t)(row0 + 8) * GN + col;
        *(half2*)p0 = __floats2half2_rn(o[j][0] * inv0, o[j][1] * inv0);
        *(half2*)p1 = __floats2half2_rn(o[j][2] * inv1, o[j][3] * inv1);
    }
}

// ============================================================================
// Launch
// ============================================================================
extern "C" void kernel_launch(void* const* d_in, const int* in_sizes, int n_in,
                              void* d_out, int out_size)
{
    const float* q  = (const float*)d_in[0];
    const float* k  = (const float*)d_in[1];
    const float* v  = (const float*)d_in[2];
    const float* Wq = (const float*)d_in[3];
    const float* bq = (const float*)d_in[4];
    const float* Wk = (const float*)d_in[5];
    const float* bk = (const float*)d_in[6];
    const float* Wv = (const float*)d_in[7];
    const float* bv = (const float*)d_in[8];
    const float* Wo = (const float*)d_in[9];
    const float* bo = (const float*)d_in[10];
    float* out = (float*)d_out;

    __half *hQ, *hK, *hV, *hC, *a16, *w16, *wo16;
    cudaGetSymbolAddress((void**)&hQ, g_hQ);
    cudaGetSymbolAddress((void**)&hK, g_hK);
    cudaGetSymbolAddress((void**)&hV, g_hV);
    cudaGetSymbolAddress((void**)&hC, g_hC);
    cudaGetSymbolAddress((void**)&a16, g_a16);
    cudaGetSymbolAddress((void**)&w16, g_w16);
    cudaGetSymbolAddress((void**)&wo16, g_wo16);

    __half* a0 = a16;
    __half* a1 = a16 + (size_t)GM * GK;
    __half* a2 = a16 + 2 * (size_t)GM * GK;
    __half* w0 = w16;
    __half* w1 = w16 + (size_t)GN * GK;
    __half* w2 = w16 + 2 * (size_t)GN * GK;

    const int n4_act = GM * GK / 4;
    const int n4_w   = GN * GK / 4;

    conv_fp16_x3<<<dim3(n4_act / 256, 3), 256>>>(
        (const float4*)q, (const float4*)k, (const float4*)v,
        (half2*)a0, (half2*)a1, (half2*)a2, n4_act);
    conv_fp16_x3<<<dim3(n4_w / 256, 3), 256>>>(
        (const float4*)Wq, (const float4*)Wk, (const float4*)Wv,
        (half2*)w0, (half2*)w1, (half2*)w2, n4_w);
    conv_fp16_1<<<n4_w / 256, 256>>>((const float4*)Wo, (half2*)wo16, n4_w);

    cudaFuncSetAttribute(gemm_qkv_fp16, cudaFuncAttributeMaxDynamicSharedMemorySize, GEMM_SMEM);
    cudaFuncSetAttribute(gemm_o_fp16, cudaFuncAttributeMaxDynamicSharedMemorySize, GEMM_SMEM);

    gemm_qkv_fp16<<<dim3(GN / BN, GM / BM, 3), 256, GEMM_SMEM>>>(
        a0, a1, a2, w0, w1, w2, bq, bk, bv, hQ, hK, hV);

    cudaFuncSetAttribute(attn_mma, cudaFuncAttributeMaxDynamicSharedMemorySize, ATTN_SMEM);
    attn_mma<<<dim3(SQ / BQ, NH, NB), 256, ATTN_SMEM>>>(hQ, hK, hV, hC);

    gemm_o_fp16<<<dim3(GN / BN, GM / BM), 256, GEMM_SMEM>>>(hC, wo16, bo, out);
}

// round 16
// speedup vs baseline: 1.0456x; 1.0104x over previous
#include <cuda_runtime.h>
#include <cuda_fp16.h>
#include <cstdint>
#include <math.h>

// Problem constants
#define GM 8192      // B*S
#define GN 1024      // D_MODEL
#define GK 1024      // D_MODEL
#define SQ 2048      // S
#define NB 4         // B
#define NH 16        // heads
#define DKH 64       // d_k per head

// Scratch (allocation-free rule: __device__ globals)
__device__ __half g_hQ[(size_t)GM * GN];
__device__ __half g_hK[(size_t)GM * GN];
__device__ __half g_hV[(size_t)GM * GN];
__device__ __half g_hC[(size_t)GM * GN];      // fp16 ctx
__device__ __half g_a16[3][(size_t)GM * GK];  // fp16 activations (q,k,v)
__device__ __half g_w16[3][(size_t)GN * GK];  // fp16 weights (Wq,Wk,Wv)
__device__ __half g_wo16[(size_t)GN * GK];    // fp16 Wo

__device__ __forceinline__ uint32_t smem_u32(const void* p) {
    uint32_t a;
    asm("{ .reg .u64 t; cvta.to.shared.u64 t, %1; cvt.u32.u64 %0, t; }"
        : "=r"(a) : "l"(p));
    return a;
}

__device__ __forceinline__ void cp_async16(uint32_t sm, const void* g) {
    asm volatile("cp.async.cg.shared.global [%0], [%1], 16;\n"
                 :: "r"(sm), "l"(g));
}
#define CP_COMMIT() asm volatile("cp.async.commit_group;\n" ::: "memory")
#define CP_WAIT(N)  asm volatile("cp.async.wait_group %0;\n" :: "n"(N) : "memory")

__device__ __forceinline__ void ldmx4(uint32_t* r, uint32_t addr) {
    asm volatile("ldmatrix.sync.aligned.m8n8.x4.shared.b16 {%0,%1,%2,%3}, [%4];"
                 : "=r"(r[0]), "=r"(r[1]), "=r"(r[2]), "=r"(r[3]) : "r"(addr));
}
__device__ __forceinline__ void ldmx4t(uint32_t* r, uint32_t addr) {
    asm volatile("ldmatrix.sync.aligned.m8n8.x4.trans.shared.b16 {%0,%1,%2,%3}, [%4];"
                 : "=r"(r[0]), "=r"(r[1]), "=r"(r[2]), "=r"(r[3]) : "r"(addr));
}

__device__ __forceinline__ void mma_fp(float* c, const uint32_t* a,
                                       uint32_t b0, uint32_t b1) {
    asm volatile(
        "mma.sync.aligned.m16n8k16.row.col.f32.f16.f16.f32 "
        "{%0,%1,%2,%3}, {%4,%5,%6,%7}, {%8,%9}, {%0,%1,%2,%3};"
        : "+f"(c[0]), "+f"(c[1]), "+f"(c[2]), "+f"(c[3])
        : "r"(a[0]), "r"(a[1]), "r"(a[2]), "r"(a[3]), "r"(b0), "r"(b1));
}

__device__ __forceinline__ uint32_t pack_h2(float x, float y) {
    const half2 h = __floats2half2_rn(x, y);
    return *reinterpret_cast<const uint32_t*>(&h);
}

// ============================================================================
// fp32 -> fp16 converts: 8 floats/thread, one 16B store (value-identical).
//   conv_act3: q,k,v (z selects). conv_w4: Wq,Wk,Wv,Wo (z selects).
// ============================================================================
__global__ __launch_bounds__(256) void conv_act3(
    const float4* __restrict__ s0, const float4* __restrict__ s1,
    const float4* __restrict__ s2, uint4* __restrict__ d0,
    uint4* __restrict__ d1, uint4* __restrict__ d2, int n8)
{
    const int z = blockIdx.y;
    const float4* src = (z == 0) ? s0 : (z == 1) ? s1 : s2;
    uint4* dst = (z == 0) ? d0 : (z == 1) ? d1 : d2;
    const int i = blockIdx.x * 256 + threadIdx.x;
    if (i >= n8) return;
    const float4 va = src[2 * i];
    const float4 vb = src[2 * i + 1];
    uint4 o;
    o.x = pack_h2(va.x, va.y);
    o.y = pack_h2(va.z, va.w);
    o.z = pack_h2(vb.x, vb.y);
    o.w = pack_h2(vb.z, vb.w);
    dst[i] = o;
}

__global__ __launch_bounds__(256) void conv_w4(
    const float4* __restrict__ s0, const float4* __restrict__ s1,
    const float4* __restrict__ s2, const float4* __restrict__ s3,
    uint4* __restrict__ d0, uint4* __restrict__ d1,
    uint4* __restrict__ d2, uint4* __restrict__ d3, int n8)
{
    const int z = blockIdx.y;
    const float4* src = (z == 0) ? s0 : (z == 1) ? s1 : (z == 2) ? s2 : s3;
    uint4* dst = (z == 0) ? d0 : (z == 1) ? d1 : (z == 2) ? d2 : d3;
    const int i = blockIdx.x * 256 + threadIdx.x;
    if (i >= n8) return;
    const float4 va = src[2 * i];
    const float4 vb = src[2 * i + 1];
    uint4 o;
    o.x = pack_h2(va.x, va.y);
    o.y = pack_h2(va.z, va.w);
    o.z = pack_h2(vb.x, vb.y);
    o.w = pack_h2(vb.z, vb.w);
    dst[i] = o;
}

// ============================================================================
// GEMM geometry (R9/R12 measured-optimum): 128x128 CTA tile, 32x64 warp tile,
//   BK=32 per stage, 3 stages, 1 sync/iter, 2 CTAs/SM.
//   Prefetch at END of iteration body (measured-best placement).
// ============================================================================
#define BM 128
#define BN 128
#define BKC 32
#define PADK 40
#define GEMM_SMEM (3 * (BM + BN) * PADK * 2)   // 61440 B

// ============================================================================
// Single-pass fp16 GEMM for Q/K/V projections, fused via blockIdx.z.
// ============================================================================
__global__ __launch_bounds__(256, 2) void gemm_qkv_fp16(
    const __half* __restrict__ A0, const __half* __restrict__ A1,
    const __half* __restrict__ A2, const __half* __restrict__ W0,
    const __half* __restrict__ W1, const __half* __restrict__ W2,
    const float* __restrict__ b0p, const float* __restrict__ b1p,
    const float* __restrict__ b2p, __half* __restrict__ C0,
    __half* __restrict__ C1, __half* __restrict__ C2)
{
    extern __shared__ __half dynsm[];
    __half* smA = dynsm;                         // [3][BM*PADK]
    __half* smB = dynsm + 3 * BM * PADK;         // [3][BN*PADK]

    const int z = blockIdx.z;
    const __half* A = (z == 0) ? A0 : (z == 1) ? A1 : A2;
    const __half* W = (z == 0) ? W0 : (z == 1) ? W1 : W2;
    const float* bias = (z == 0) ? b0p : (z == 1) ? b1p : b2p;
    __half* C = (z == 0) ? C0 : (z == 1) ? C1 : C2;

    const int tid  = threadIdx.x;
    const int wid  = tid >> 5;
    const int lane = tid & 31;
    const int wm   = wid & 3;
    const int wn   = wid >> 2;
    const int m0   = blockIdx.y * BM;
    const int n0   = blockIdx.x * BN;

    const int crow = tid >> 1;
    const int cs0  = (tid & 1) * 2;
    const int lr = lane & 15;
    const int lc = (lane >> 4) * 8;

    float acc[2][8][4];
#pragma unroll
    for (int i = 0; i < 2; i++)
#pragma unroll
        for (int j = 0; j < 8; j++)
#pragma unroll
            for (int k = 0; k < 4; k++) acc[i][j][k] = 0.0f;

    const uint32_t smA0 = smem_u32(smA);
    const uint32_t smB0 = smem_u32(smB);

    auto issue_copy = [&](int it, int st) {
        const int kb = it * BKC;
        const __half* Ab = A + (size_t)(m0 + crow) * GK + kb;
        const __half* Bb = W + (size_t)(n0 + crow) * GK + kb;
        const uint32_t sa = smA0 + (st * BM * PADK + crow * PADK) * 2;
        const uint32_t sb = smB0 + (st * BN * PADK + crow * PADK) * 2;
#pragma unroll
        for (int s = 0; s < 2; s++) {
            cp_async16(sa + (cs0 + s) * 16, Ab + (cs0 + s) * 8);
            cp_async16(sb + (cs0 + s) * 16, Bb + (cs0 + s) * 8);
        }
        CP_COMMIT();
    };

    const int NIT1 = GK / BKC;   // 32
    issue_copy(0, 0);
    issue_copy(1, 1);

    for (int it = 0; it < NIT1; it++) {
        const int st = it % 3;
        if (it + 1 < NIT1) { CP_WAIT(1); } else { CP_WAIT(0); }
        __syncthreads();

        const uint32_t baseA = smA0 + st * BM * PADK * 2;
        const uint32_t baseB = smB0 + st * BN * PADK * 2;
#pragma unroll
        for (int ks = 0; ks < 2; ks++) {
            uint32_t a[2][4], b[4][4];
#pragma unroll
            for (int am = 0; am < 2; am++) {
                const int row = wm * 32 + am * 16 + lr;
                ldmx4(a[am], baseA + (row * PADK + ks * 16 + lc) * 2);
            }
#pragma unroll
            for (int bn = 0; bn < 4; bn++) {
                const int row = wn * 64 + bn * 16 + lr;
                ldmx4(b[bn], baseB + (row * PADK + ks * 16 + lc) * 2);
            }
#pragma unroll
            for (int am = 0; am < 2; am++)
#pragma unroll
                for (int bn = 0; bn < 4; bn++) {
                    mma_fp(acc[am][2 * bn + 0], a[am], b[bn][0], b[bn][2]);
                    mma_fp(acc[am][2 * bn + 1], a[am], b[bn][1], b[bn][3]);
                }
        }
        if (it + 2 < NIT1) issue_copy(it + 2, (it + 2) % 3);
    }

    const int er = lane >> 2;
    const int ec = (lane & 3) * 2;
#pragma unroll
    for (int am = 0; am < 2; am++) {
        const int row = m0 + wm * 32 + am * 16 + er;
#pragma unroll
        for (int bn = 0; bn < 8; bn++) {
            const int col = n0 + wn * 64 + bn * 8 + ec;
            const float bx = bias[col], by = bias[col + 1];
            *(half2*)(C + (size_t)row * GN + col) =
                __floats2half2_rn(acc[am][bn][0] + bx, acc[am][bn][1] + by);
            *(half2*)(C + (size_t)(row + 8) * GN + col) =
                __floats2half2_rn(acc[am][bn][2] + bx, acc[am][bn][3] + by);
        }
    }
}

// ============================================================================
// O projection: single-pass fp16 GEMM, fp32 out. Same geometry.
// ============================================================================
__global__ __launch_bounds__(256, 2) void gemm_o_fp16(
    const __half* __restrict__ A, const __half* __restrict__ W,
    const float* __restrict__ bias, float* __restrict__ C)
{
    extern __shared__ __half dynsm[];
    __half* smA = dynsm;
    __half* smB = dynsm + 3 * BM * PADK;

    const int tid  = threadIdx.x;
    const int wid  = tid >> 5;
    const int lane = tid & 31;
    const int wm   = wid & 3;
    const int wn   = wid >> 2;
    const int m0   = blockIdx.y * BM;
    const int n0   = blockIdx.x * BN;

    const int crow = tid >> 1;
    const int cs0  = (tid & 1) * 2;
    const int lr = lane & 15;
    const int lc = (lane >> 4) * 8;

    float acc[2][8][4];
#pragma unroll
    for (int i = 0; i < 2; i++)
#pragma unroll
        for (int j = 0; j < 8; j++)
#pragma unroll
            for (int k = 0; k < 4; k++) acc[i][j][k] = 0.0f;

    const uint32_t smA0 = smem_u32(smA);
    const uint32_t smB0 = smem_u32(smB);

    auto issue_copy = [&](int it, int st) {
        const int kb = it * BKC;
        const __half* Ab = A + (size_t)(m0 + crow) * GK + kb;
        const __half* Bb = W + (size_t)(n0 + crow) * GK + kb;
        const uint32_t sa = smA0 + (st * BM * PADK + crow * PADK) * 2;
        const uint32_t sb = smB0 + (st * BN * PADK + crow * PADK) * 2;
#pragma unroll
        for (int s = 0; s < 2; s++) {
            cp_async16(sa + (cs0 + s) * 16, Ab + (cs0 + s) * 8);
            cp_async16(sb + (cs0 + s) * 16, Bb + (cs0 + s) * 8);
        }
        CP_COMMIT();
    };

    const int NIT1 = GK / BKC;   // 32
    issue_copy(0, 0);
    issue_copy(1, 1);

    for (int it = 0; it < NIT1; it++) {
        const int st = it % 3;
        if (it + 1 < NIT1) { CP_WAIT(1); } else { CP_WAIT(0); }
        __syncthreads();

        const uint32_t baseA = smA0 + st * BM * PADK * 2;
        const uint32_t baseB = smB0 + st * BN * PADK * 2;
#pragma unroll
        for (int ks = 0; ks < 2; ks++) {
            uint32_t a[2][4], b[4][4];
#pragma unroll
            for (int am = 0; am < 2; am++) {
                const int row = wm * 32 + am * 16 + lr;
                ldmx4(a[am], baseA + (row * PADK + ks * 16 + lc) * 2);
            }
#pragma unroll
            for (int bn = 0; bn < 4; bn++) {
                const int row = wn * 64 + bn * 16 + lr;
                ldmx4(b[bn], baseB + (row * PADK + ks * 16 + lc) * 2);
            }
#pragma unroll
            for (int am = 0; am < 2; am++)
#pragma unroll
                for (int bn = 0; bn < 4; bn++) {
                    mma_fp(acc[am][2 * bn + 0], a[am], b[bn][0], b[bn][2]);
                    mma_fp(acc[am][2 * bn + 1], a[am], b[bn][1], b[bn][3]);
                }
        }
        if (it + 2 < NIT1) issue_copy(it + 2, (it + 2) % 3);
    }

    const int er = lane >> 2;
    const int ec = (lane & 3) * 2;
#pragma unroll
    for (int am = 0; am < 2; am++) {
        const int row = m0 + wm * 32 + am * 16 + er;
#pragma unroll
        for (int bn = 0; bn < 8; bn++) {
            const int col = n0 + wn * 64 + bn * 8 + ec;
            const float bx = bias[col], by = bias[col + 1];
            *(float2*)(C + (size_t)row * GN + col) =
                make_float2(acc[am][bn][0] + bx, acc[am][bn][1] + by);
            *(float2*)(C + (size_t)(row + 8) * GN + col) =
                make_float2(acc[am][bn][2] + bx, acc[am][bn][3] + by);
        }
    }
}

// ============================================================================
// Fused flash attention, fp16 mma.sync, BKV=128, register-resident P,
//   exp2-domain softmax, 3-stage K/V pipeline, ONE barrier per tile. (R14)
// ============================================================================
#define BQ 128
#define BKV 128
#define QS 72
#define NTKV (SQ / BKV)   // 16
#define NSTG 3
#define ATTN_SMEM ((BQ * QS + 2 * NSTG * BKV * QS) * 2)   // 129024 B
#define SC2 0.1803368801111f   // 0.125 * log2(e)

__global__ __launch_bounds__(256, 1) void attn_mma(
    const __half* __restrict__ Qh, const __half* __restrict__ Kh,
    const __half* __restrict__ Vh, __half* __restrict__ Ctx)
{
    extern __shared__ __half sm[];
    __half* sQ = sm;                      // [128][QS]
    __half* sK = sQ + BQ * QS;            // [3][128][QS]
    __half* sV = sK + NSTG * BKV * QS;    // [3][128][QS]

    const int tid  = threadIdx.x;
    const int wid  = tid >> 5;
    const int lane = tid & 31;
    const int lr   = lane & 15;
    const int lc   = (lane >> 4) * 8;
    const int er   = lane >> 2;
    const int ec   = (lane & 3) * 2;
    const int wrow = wid * 16;

    const int q0 = blockIdx.x * BQ;
    const size_t hb = ((size_t)blockIdx.z * SQ) * (size_t)GN + (size_t)blockIdx.y * DKH;

    const uint32_t sQb = smem_u32(sQ);
    const uint32_t sKb = smem_u32(sK);
    const uint32_t sVb = smem_u32(sV);

    const int crow = tid >> 1;
    const int cs0  = (tid & 1) * 4;

    auto loadKV = [&](int kt, int st) {
        const __half* kp = Kh + hb + (size_t)(kt * BKV + crow) * GN;
        const __half* vp = Vh + hb + (size_t)(kt * BKV + crow) * GN;
        const uint32_t dk = sKb + (st * BKV * QS + crow * QS) * 2;
        const uint32_t dv = sVb + (st * BKV * QS + crow * QS) * 2;
#pragma unroll
        for (int s = 0; s < 4; s++) {
            cp_async16(dk + (cs0 + s) * 16, kp + (cs0 + s) * 8);
            cp_async16(dv + (cs0 + s) * 16, vp + (cs0 + s) * 8);
        }
        CP_COMMIT();
    };

    {   // Q load (own commit group)
        const __half* qp = Qh + hb + (size_t)(q0 + crow) * GN;
        const uint32_t dq = sQb + (crow * QS) * 2;
#pragma unroll
        for (int s = 0; s < 4; s++)
            cp_async16(dq + (cs0 + s) * 16, qp + (cs0 + s) * 8);
        CP_COMMIT();
    }
    loadKV(0, 0);
    loadKV(1, 1);

    float m0r = -1.0e30f, m1r = -1.0e30f, l0 = 0.0f, l1 = 0.0f;
    float o[8][4];
#pragma unroll
    for (int j = 0; j < 8; j++)
#pragma unroll
        for (int k = 0; k < 4; k++) o[j][k] = 0.0f;

    uint32_t aq[4][4];   // Q fragments, loaded once

    for (int kt = 0; kt < NTKV; kt++) {
        if (kt < NTKV - 1) { CP_WAIT(1); } else { CP_WAIT(0); }
        __syncthreads();
        // 3-stage: write target (kt+2)%3 was read in tile kt-1, whose readers
        // are all past the barrier above -> safe without a second barrier.
        if (kt + 2 < NTKV) loadKV(kt + 2, (kt + 2) % NSTG);
        if (kt == 0) {
#pragma unroll
            for (int ks = 0; ks < 4; ks++)
                ldmx4(aq[ks], sQb + ((wrow + lr) * QS + ks * 16 + lc) * 2);
        }
        const int st = kt % NSTG;
        const uint32_t kbase = sKb + st * BKV * QS * 2;
        const uint32_t vbase = sVb + st * BKV * QS * 2;

        // ---- S = Q K^T (16 x 128 per warp) ----
        float s[16][4];
#pragma unroll
        for (int t = 0; t < 16; t++)
#pragma unroll
            for (int k = 0; k < 4; k++) s[t][k] = 0.0f;

#pragma unroll
        for (int ks = 0; ks < 4; ks++) {
#pragma unroll
            for (int nt = 0; nt < 8; nt++) {
                uint32_t b[4];
                ldmx4(b, kbase + ((nt * 16 + lr) * QS + ks * 16 + lc) * 2);
                mma_fp(s[2 * nt + 0], aq[ks], b[0], b[2]);
                mma_fp(s[2 * nt + 1], aq[ks], b[1], b[3]);
            }
        }

        // ---- online softmax in log2 domain; P packed into A-frags ----
        float mx0 = -1.0e30f, mx1 = -1.0e30f;
#pragma unroll
        for (int t = 0; t < 16; t++) {
            mx0 = fmaxf(mx0, fmaxf(s[t][0], s[t][1]));
            mx1 = fmaxf(mx1, fmaxf(s[t][2], s[t][3]));
        }
        mx0 = fmaxf(mx0, __shfl_xor_sync(0xffffffffu, mx0, 1));
        mx0 = fmaxf(mx0, __shfl_xor_sync(0xffffffffu, mx0, 2));
        mx1 = fmaxf(mx1, __shfl_xor_sync(0xffffffffu, mx1, 1));
        mx1 = fmaxf(mx1, __shfl_xor_sync(0xffffffffu, mx1, 2));
        mx0 *= SC2;
        mx1 *= SC2;
        const float mn0 = fmaxf(m0r, mx0);
        const float mn1 = fmaxf(m1r, mx1);
        const float c0 = exp2f(m0r - mn0);
        const float c1 = exp2f(m1r - mn1);

        float rs0 = 0.0f, rs1 = 0.0f;
        uint32_t pw[16][2];
#pragma unroll
        for (int t = 0; t < 16; t++) {
            const float p00 = exp2f(fmaf(s[t][0], SC2, -mn0));
            const float p01 = exp2f(fmaf(s[t][1], SC2, -mn0));
            const float p10 = exp2f(fmaf(s[t][2], SC2, -mn1));
            const float p11 = exp2f(fmaf(s[t][3], SC2, -mn1));
            rs0 += p00 + p01;
            rs1 += p10 + p11;
            pw[t][0] = pack_h2(p00, p01);
            pw[t][1] = pack_h2(p10, p11);
        }
        rs0 += __shfl_xor_sync(0xffffffffu, rs0, 1);
        rs0 += __shfl_xor_sync(0xffffffffu, rs0, 2);
        rs1 += __shfl_xor_sync(0xffffffffu, rs1, 1);
        rs1 += __shfl_xor_sync(0xffffffffu, rs1, 2);
        l0 = l0 * c0 + rs0;
        l1 = l1 * c1 + rs1;
        m0r = mn0;
        m1r = mn1;
#pragma unroll
        for (int j = 0; j < 8; j++) {
            o[j][0] *= c0; o[j][1] *= c0;
            o[j][2] *= c1; o[j][3] *= c1;
        }

        // ---- O += P V (P from registers, V via ldmatrix.trans) ----
#pragma unroll
        for (int j = 0; j < 8; j++) {      // 16-key chunks
            const uint32_t pa[4] = {pw[2 * j][0], pw[2 * j][1],
                                    pw[2 * j + 1][0], pw[2 * j + 1][1]};
#pragma unroll
            for (int dt = 0; dt < 4; dt++) {
                uint32_t vb[4];
                ldmx4t(vb, vbase + ((j * 16 + lr) * QS + dt * 16 + lc) * 2);
                mma_fp(o[2 * dt + 0], pa, vb[0], vb[1]);
                mma_fp(o[2 * dt + 1], pa, vb[2], vb[3]);
            }
        }
    }

    const float inv0 = 1.0f / l0;
    const float inv1 = 1.0f / l1;
    const int row0 = q0 + wrow + er;
#pragma unroll
    for (int j = 0; j < 8; j++) {
        const int col = j * 8 + ec;
        __half* p0 = Ctx + hb + (size_t)row0 * GN + col;
        __half* p1 = Ctx + hb + (size_t)(row0 + 8) * GN + col;
        *(half2*)p0 = __floats2half2_rn(o[j][0] * inv0, o[j][1] * inv0);
        *(half2*)p1 = __floats2half2_rn(o[j][2] * inv1, o[j][3] * inv1);
    }
}

// ============================================================================
// Launch
// ============================================================================
extern "C" void kernel_launch(void* const* d_in, const int* in_sizes, int n_in,
                              void* d_out, int out_size)
{
    const float* q  = (const float*)d_in[0];
    const float* k  = (const float*)d_in[1];
    const float* v  = (const float*)d_in[2];
    const float* Wq = (const float*)d_in[3];
    const float* bq = (const float*)d_in[4];
    const float* Wk = (const float*)d_in[5];
    const float* bk = (const float*)d_in[6];
    const float* Wv = (const float*)d_in[7];
    const float* bv = (const float*)d_in[8];
    const float* Wo = (const float*)d_in[9];
    const float* bo = (const float*)d_in[10];
    float* out = (float*)d_out;

    __half *hQ, *hK, *hV, *hC, *a16, *w16, *wo16;
    cudaGetSymbolAddress((void**)&hQ, g_hQ);
    cudaGetSymbolAddress((void**)&hK, g_hK);
    cudaGetSymbolAddress((void**)&hV, g_hV);
    cudaGetSymbolAddress((void**)&hC, g_hC);
    cudaGetSymbolAddress((void**)&a16, g_a16);
    cudaGetSymbolAddress((void**)&w16, g_w16);
    cudaGetSymbolAddress((void**)&wo16, g_wo16);

    __half* a0 = a16;
    __half* a1 = a16 + (size_t)GM * GK;
    __half* a2 = a16 + 2 * (size_t)GM * GK;
    __half* w0 = w16;
    __half* w1 = w16 + (size_t)GN * GK;
    __half* w2 = w16 + 2 * (size_t)GN * GK;

    const int n8_act = GM * GK / 8;   // 1048576
    const int n8_w   = GN * GK / 8;   // 131072

    conv_act3<<<dim3(n8_act / 256, 3), 256>>>(
        (const float4*)q, (const float4*)k, (const float4*)v,
        (uint4*)a0, (uint4*)a1, (uint4*)a2, n8_act);
    conv_w4<<<dim3(n8_w / 256, 4), 256>>>(
        (const float4*)Wq, (const float4*)Wk, (const float4*)Wv,
        (const float4*)Wo,
        (uint4*)w0, (uint4*)w1, (uint4*)w2, (uint4*)wo16, n8_w);

    cudaFuncSetAttribute(gemm_qkv_fp16, cudaFuncAttributeMaxDynamicSharedMemorySize, GEMM_SMEM);
    cudaFuncSetAttribute(gemm_o_fp16, cudaFuncAttributeMaxDynamicSharedMemorySize, GEMM_SMEM);

    gemm_qkv_fp16<<<dim3(GN / BN, GM / BM, 3), 256, GEMM_SMEM>>>(
        a0, a1, a2, w0, w1, w2, bq, bk, bv, hQ, hK, hV);

    cudaFuncSetAttribute(attn_mma, cudaFuncAttributeMaxDynamicSharedMemorySize, ATTN_SMEM);
    attn_mma<<<dim3(SQ / BQ, NH, NB), 256, ATTN_SMEM>>>(hQ, hK, hV, hC);

    gemm_o_fp16<<<dim3(GN / BN, GM / BM), 256, GEMM_SMEM>>>(hC, wo16, bo, out);
}